// round 12
// baseline (speedup 1.0000x reference)
#include <cuda_runtime.h>
#include <cuda_bf16.h>
#include <math.h>
#include <cstdint>

#define NOBS   8192
#define NTOP   128
#define NDIM   64
#define NBATCH 8192
#define NROWS  (NOBS + NBATCH)
#define NTILE  64           // number of 128x128 tiles per dim (8192/128)
#define NTRI   2080         // triangular tile count = 64*65/2
#define NPCTA  296          // persistent CTAs (2 per SM)

// ------------------------- scratch (no cudaMalloc) -------------------------
__device__ float  g_Z[NROWS * NTOP];
__device__ float  g_X[NOBS * NDIM];    // tf32-rounded embedded points
__device__ float  g_sq[NOBS];          // sq norms of rounded points
__device__ float  g_den[NBATCH];       // ||xi-xj||^2 per batch element
__device__ double g_part;
__device__ int    g_ctr;

// ------------------------- helpers -----------------------------------------
__device__ __forceinline__ uint32_t smem_u32(const void* p) {
    uint32_t a;
    asm("{ .reg .u64 t; cvta.to.shared.u64 t, %1; cvt.u32.u64 %0, t; }" : "=r"(a) : "l"(p));
    return a;
}
__device__ __forceinline__ void cp16(uint32_t dst, const void* src) {
    asm volatile("{ .reg .u64 g; cvta.to.global.u64 g, %1; "
                 "cp.async.cg.shared.global [%0], [g], 16; }"
                 :: "r"(dst), "l"(src));
}
#define CP_COMMIT() asm volatile("cp.async.commit_group;" ::: "memory")
#define CP_WAIT0()  asm volatile("cp.async.wait_group 0;" ::: "memory")

__device__ __forceinline__ float fast_log_unit(float t) {
    float s = t - 1.0f;
    float p = fmaf(s, -0.16666667f, 0.2f);
    p = fmaf(s, p, -0.25f);
    p = fmaf(s, p, 0.33333333f);
    p = fmaf(s, p, -0.5f);
    p = fmaf(s, p, 1.0f);
    p = s * p;
    float lg = __logf(t);
    return (t > 0.90625f) ? p : lg;
}

__device__ __forceinline__ void gumbel_softmax4(const float* __restrict__ lrow,
                                                const float* __restrict__ nrow,
                                                int lane, float z[4]) {
    float s = 0.f;
#pragma unroll
    for (int c = 0; c < 4; c++) {
        int t = lane + 32 * c;
        float w = -fast_log_unit(nrow[t] + 1e-9f) + 1e-9f;
        z[c] = __fdividef(__expf(lrow[t]), w);
        s += z[c];
    }
#pragma unroll
    for (int o = 16; o > 0; o >>= 1) s += __shfl_xor_sync(0xffffffffu, s, o);
    float inv = __fdividef(1.f, s);
#pragma unroll
    for (int c = 0; c < 4; c++) z[c] *= inv;
}

__device__ __forceinline__ float tf32_round(float x) {
    uint32_t r;
    asm("cvt.rna.tf32.f32 %0, %1;" : "=r"(r) : "f"(x));
    return __uint_as_float(r);
}
__device__ __forceinline__ uint32_t tf32_hi(float x) {
    uint32_t r;
    asm("cvt.rna.tf32.f32 %0, %1;" : "=r"(r) : "f"(x));
    return r;
}
__device__ __forceinline__ void mma_tf32(float c[4], const uint32_t a[4], const uint32_t b[2]) {
    asm volatile(
        "mma.sync.aligned.m16n8k8.row.col.f32.tf32.tf32.f32 "
        "{%0,%1,%2,%3}, {%4,%5,%6,%7}, {%8,%9}, {%0,%1,%2,%3};"
        : "+f"(c[0]), "+f"(c[1]), "+f"(c[2]), "+f"(c[3])
        : "r"(a[0]), "r"(a[1]), "r"(a[2]), "r"(a[3]), "r"(b[0]), "r"(b[1]));
}
__device__ __forceinline__ float rcp_approx(float x) {
    float r;
    asm("rcp.approx.f32 %0, %1;" : "=f"(r) : "f"(x));
    return r;
}

// ---------------------------------------------------------------------------
// K0: softmax rows (full) + diff rows (batch); zero accumulators + counter.
// ---------------------------------------------------------------------------
__global__ void __launch_bounds__(256) k_z(const float* __restrict__ logits,
                                           const float* __restrict__ noise_full,
                                           const float* __restrict__ noise_i,
                                           const float* __restrict__ noise_j,
                                           const int* __restrict__ iv,
                                           const int* __restrict__ jv) {
    int tid = threadIdx.x, w = tid >> 5, lane = tid & 31;
    int row = blockIdx.x * 8 + w;
    int gz = blockIdx.x * 256 + tid;
    if (gz < NOBS)   g_sq[gz] = 0.f;
    if (gz < NBATCH) g_den[gz] = 0.f;
    if (gz == 0)     { g_part = 0.0; g_ctr = 0; }

    if (row < NOBS) {
        float z[4];
        gumbel_softmax4(logits + (size_t)row * NTOP, noise_full + (size_t)row * NTOP, lane, z);
#pragma unroll
        for (int c = 0; c < 4; c++) g_Z[(size_t)row * NTOP + lane + 32 * c] = z[c];
    } else {
        int el = row - NOBS;
        int ri = iv[el], rj = jv[el];
        float zi[4], zj[4];
        gumbel_softmax4(logits + (size_t)ri * NTOP, noise_i + (size_t)el * NTOP, lane, zi);
        gumbel_softmax4(logits + (size_t)rj * NTOP, noise_j + (size_t)el * NTOP, lane, zj);
#pragma unroll
        for (int c = 0; c < 4; c++)
            g_Z[(size_t)row * NTOP + lane + 32 * c] = zi[c] - zj[c];
    }
}

// ---------------------------------------------------------------------------
// K1: X = Z @ W^T (tf32 x3, fp32-equivalent). Fused epilogue:
//   rows < NOBS: store rounded x to g_X, atomic row-sumsq -> g_sq
//   rows >= NOBS: atomic row-sumsq -> g_den
// ---------------------------------------------------------------------------
#define G_ZS 0
#define G_WS 32768
#define SMEM_G 65536

__global__ void __launch_bounds__(256, 2) k_gemm(const float* __restrict__ W) {
    extern __shared__ char sm[];
    int tid = threadIdx.x;
    int base = blockIdx.x * 64;

    {
        const uint4* srcZ = (const uint4*)(g_Z + (size_t)base * NTOP);
        const uint4* srcW = (const uint4*)W;
#pragma unroll
        for (int it = 0; it < 8; it++) {
            int idx = it * 256 + tid;
            int off = idx * 16;
            int row = off >> 9;
            uint32_t sw = (uint32_t)(off & ~511) | (uint32_t)((off & 511) ^ ((row & 7) << 4));
            *(uint4*)(sm + G_ZS + sw) = srcZ[idx];
            *(uint4*)(sm + G_WS + sw) = srcW[idx];
        }
    }
    __syncthreads();

    int lane = tid & 31, w = tid >> 5;
    int mw = (w >> 2) * 32;
    int nw = (w & 3) * 16;
    int g = lane >> 2, t = lane & 3;

    float c[2][2][4];
#pragma unroll
    for (int mt = 0; mt < 2; mt++)
#pragma unroll
        for (int nt = 0; nt < 2; nt++)
#pragma unroll
            for (int q = 0; q < 4; q++) c[mt][nt][q] = 0.f;

#pragma unroll
    for (int ks = 0; ks < 16; ks++) {
        int c0 = (ks * 32 + 4 * t) ^ (g << 4);
        int c1 = (ks * 32 + 4 * t + 16) ^ (g << 4);

        uint32_t bh[2][2], bl[2][2];
#pragma unroll
        for (int nt = 0; nt < 2; nt++) {
            const char* rn = sm + G_WS + (nw + nt * 8 + g) * 512;
            float b0 = *(const float*)(rn + c0);
            float b1 = *(const float*)(rn + c1);
            bh[nt][0] = tf32_hi(b0);
            bh[nt][1] = tf32_hi(b1);
            bl[nt][0] = tf32_hi(b0 - __uint_as_float(bh[nt][0]));
            bl[nt][1] = tf32_hi(b1 - __uint_as_float(bh[nt][1]));
        }
        uint32_t ah[2][4], al[2][4];
#pragma unroll
        for (int mt = 0; mt < 2; mt++) {
            const char* r0 = sm + G_ZS + (mw + mt * 16 + g) * 512;
            const char* r1 = r0 + 8 * 512;
            float a0 = *(const float*)(r0 + c0);
            float a1 = *(const float*)(r1 + c0);
            float a2 = *(const float*)(r0 + c1);
            float a3 = *(const float*)(r1 + c1);
            ah[mt][0] = tf32_hi(a0); al[mt][0] = tf32_hi(a0 - __uint_as_float(ah[mt][0]));
            ah[mt][1] = tf32_hi(a1); al[mt][1] = tf32_hi(a1 - __uint_as_float(ah[mt][1]));
            ah[mt][2] = tf32_hi(a2); al[mt][2] = tf32_hi(a2 - __uint_as_float(ah[mt][2]));
            ah[mt][3] = tf32_hi(a3); al[mt][3] = tf32_hi(a3 - __uint_as_float(ah[mt][3]));
        }
#pragma unroll
        for (int mt = 0; mt < 2; mt++)
#pragma unroll
            for (int nt = 0; nt < 2; nt++) {
                mma_tf32(c[mt][nt], ah[mt], bh[nt]);
                mma_tf32(c[mt][nt], al[mt], bh[nt]);
                mma_tf32(c[mt][nt], ah[mt], bl[nt]);
            }
    }

    bool zrows = (base < NOBS);
#pragma unroll
    for (int mt = 0; mt < 2; mt++) {
        int m0 = base + mw + mt * 16 + g;
        float r0 = 0.f, r1 = 0.f;
#pragma unroll
        for (int nt = 0; nt < 2; nt++) {
            int n0 = nw + nt * 8 + 2 * t;
            float v00 = c[mt][nt][0], v01 = c[mt][nt][1];
            float v10 = c[mt][nt][2], v11 = c[mt][nt][3];
            if (zrows) {
                v00 = tf32_round(v00); v01 = tf32_round(v01);
                v10 = tf32_round(v10); v11 = tf32_round(v11);
                g_X[(size_t)m0 * NDIM + n0]           = v00;
                g_X[(size_t)m0 * NDIM + n0 + 1]       = v01;
                g_X[(size_t)(m0 + 8) * NDIM + n0]     = v10;
                g_X[(size_t)(m0 + 8) * NDIM + n0 + 1] = v11;
            }
            r0 += fmaf(v00, v00, v01 * v01);
            r1 += fmaf(v10, v10, v11 * v11);
        }
        r0 += __shfl_xor_sync(0xffffffffu, r0, 1);
        r0 += __shfl_xor_sync(0xffffffffu, r0, 2);
        r1 += __shfl_xor_sync(0xffffffffu, r1, 1);
        r1 += __shfl_xor_sync(0xffffffffu, r1, 2);
        if (t == 0) {
            if (zrows) {
                atomicAdd(&g_sq[m0], r0);
                atomicAdd(&g_sq[m0 + 8], r1);
            } else {
                atomicAdd(&g_den[m0 - NOBS], r0);
                atomicAdd(&g_den[m0 + 8 - NOBS], r1);
            }
        }
    }
}

// ---------------------------------------------------------------------------
// K2: persistent pairwise + fused loss finish (last CTA).
// A panel resident; B double-buffered via cp.async; per-thread accumulation
// across tiles (no per-tile barriers); one reduction + atomic per CTA.
// ---------------------------------------------------------------------------
#define P_A    0
#define P_B0   32768
#define P_B1   65536
#define P_RED  98304
#define SMEM_PW 98368

__device__ __forceinline__ void fill_async(uint32_t smbase, const float* gsrc, int tid) {
    const char* src = (const char*)gsrc;
#pragma unroll
    for (int it = 0; it < 8; it++) {
        int off = (it * 256 + tid) * 16;
        int row = off >> 8;
        uint32_t sw = (uint32_t)(off & ~255) | (uint32_t)((off & 255) ^ ((row & 7) << 4));
        cp16(smbase + sw, src + off);
    }
}

__device__ __forceinline__ float tile_compute(char* sm, uint32_t boff,
                                              int bi, int bj, bool diag, int tid) {
    int lane = tid & 31, w = tid >> 5;
    int mw = (w >> 2) * 64;
    int nw = (w & 3) * 32;
    int g = lane >> 2, t = lane & 3;

    float c[4][4][4];
#pragma unroll
    for (int mt = 0; mt < 4; mt++)
#pragma unroll
        for (int nt = 0; nt < 4; nt++)
#pragma unroll
            for (int q = 0; q < 4; q++) c[mt][nt][q] = 0.f;

#pragma unroll
    for (int ks = 0; ks < 8; ks++) {
        int c0 = (32 * ks + 4 * t) ^ (g << 4);
        int c1 = (32 * ks + 4 * t + 16) ^ (g << 4);

        uint32_t b[4][2];
#pragma unroll
        for (int nt = 0; nt < 4; nt++) {
            const char* rn = sm + boff + (nw + nt * 8 + g) * 256;
            b[nt][0] = *(const uint32_t*)(rn + c0);
            b[nt][1] = *(const uint32_t*)(rn + c1);
        }
        uint32_t a[4][4];
#pragma unroll
        for (int mt = 0; mt < 4; mt++) {
            const char* r0 = sm + P_A + (mw + mt * 16 + g) * 256;
            const char* r1 = r0 + 8 * 256;
            a[mt][0] = *(const uint32_t*)(r0 + c0);
            a[mt][1] = *(const uint32_t*)(r1 + c0);
            a[mt][2] = *(const uint32_t*)(r0 + c1);
            a[mt][3] = *(const uint32_t*)(r1 + c1);
        }
#pragma unroll
        for (int mt = 0; mt < 4; mt++)
#pragma unroll
            for (int nt = 0; nt < 4; nt++)
                mma_tf32(c[mt][nt], a[mt], b[nt]);
    }

    float sb0[4], sb1[4];
#pragma unroll
    for (int nt = 0; nt < 4; nt++) {
        int n0 = nw + nt * 8 + 2 * t;
        sb0[nt] = g_sq[bj * 128 + n0];
        sb1[nt] = g_sq[bj * 128 + n0 + 1];
    }
    float acc = 0.f;
    if (!diag) {
        // 4-way reciprocal combining: 1 MUFU per 4 values
#pragma unroll
        for (int mt = 0; mt < 4; mt++) {
            int m0 = mw + mt * 16 + g;
            float sa0 = 1.f + g_sq[bi * 128 + m0];
            float sa1 = 1.f + g_sq[bi * 128 + m0 + 8];
#pragma unroll
            for (int nt = 0; nt < 4; nt++) {
                float x00 = fmaf(-2.f, c[mt][nt][0], sa0 + sb0[nt]);
                float x01 = fmaf(-2.f, c[mt][nt][1], sa0 + sb1[nt]);
                float x10 = fmaf(-2.f, c[mt][nt][2], sa1 + sb0[nt]);
                float x11 = fmaf(-2.f, c[mt][nt][3], sa1 + sb1[nt]);
                float s1 = x00 + x01, p1 = x00 * x01;
                float s2 = x10 + x11, p2 = x10 * x11;
                float num = fmaf(s1, p2, s2 * p1);
                acc = fmaf(num, rcp_approx(p1 * p2), acc);
            }
        }
    } else {
#pragma unroll
        for (int mt = 0; mt < 4; mt++) {
            int m0 = mw + mt * 16 + g;
            float sa0 = g_sq[bi * 128 + m0];
            float sa1 = g_sq[bi * 128 + m0 + 8];
#pragma unroll
            for (int nt = 0; nt < 4; nt++) {
                int n0 = nw + nt * 8 + 2 * t;
                float v00 = rcp_approx(fmaf(-2.f, c[mt][nt][0], 1.f + sa0 + sb0[nt]));
                float v01 = rcp_approx(fmaf(-2.f, c[mt][nt][1], 1.f + sa0 + sb1[nt]));
                float v10 = rcp_approx(fmaf(-2.f, c[mt][nt][2], 1.f + sa1 + sb0[nt]));
                float v11 = rcp_approx(fmaf(-2.f, c[mt][nt][3], 1.f + sa1 + sb1[nt]));
                if (m0 == n0) v00 = 0.f;
                if (m0 == n0 + 1) v01 = 0.f;
                if (m0 + 8 == n0) v10 = 0.f;
                if (m0 + 8 == n0 + 1) v11 = 0.f;
                acc += (v00 + v01) + (v10 + v11);
            }
        }
    }
    return acc;
}

__global__ void __launch_bounds__(256, 2) k_pairwise(const float* __restrict__ pij,
                                                     float* __restrict__ out) {
    extern __shared__ char sm[];
    uint32_t smb = smem_u32(sm);
    int tid = threadIdx.x;
    int cid = blockIdx.x;
    int lane = tid & 31, w = tid >> 5;

    int t0 = (NTRI * cid) / NPCTA;
    int t1 = (NTRI * (cid + 1)) / NPCTA;

    int bi = 0, rem = t0;
    while (rem >= NTILE - bi) { rem -= NTILE - bi; bi++; }
    int bj = bi + rem;

    fill_async(smb + P_A, g_X + (size_t)bi * 128 * NDIM, tid);
    int curbuf = 0, nextbuf = 0;
    if (bj != bi) {
        fill_async(smb + P_B0, g_X + (size_t)bj * 128 * NDIM, tid);
        nextbuf = 1;
    }
    CP_COMMIT();

    float cta_acc = 0.f;

#pragma unroll 1
    for (int t = t0; t < t1; t++) {
        int nbi = bi, nbj = bj + 1;
        if (nbj == NTILE) { nbi = bi + 1; nbj = nbi; }
        bool diag = (bi == bj);

        CP_WAIT0();
        __syncthreads();           // tile t data visible; all warps past tile t-1

        bool canPre = (t + 1 < t1) && (nbi == bi);
        if (canPre) {
            fill_async(smb + (nextbuf ? P_B1 : P_B0),
                       g_X + (size_t)nbj * 128 * NDIM, tid);
            CP_COMMIT();
        }

        float a = tile_compute(sm, diag ? P_A : (curbuf ? P_B1 : P_B0), bi, bj, diag, tid);
        cta_acc += diag ? a : 2.f * a;

        if (canPre) { curbuf = nextbuf; nextbuf ^= 1; }
        bi = nbi; bj = nbj;
        if (t + 1 < t1 && !canPre) {
            __syncthreads();       // all warps done reading old A
            fill_async(smb + P_A, g_X + (size_t)bi * 128 * NDIM, tid);
            CP_COMMIT();
        }
    }

    // single CTA reduction + atomic
#pragma unroll
    for (int o = 16; o > 0; o >>= 1) cta_acc += __shfl_xor_sync(0xffffffffu, cta_acc, o);
    float* red = (float*)(sm + P_RED);
    if (lane == 0) red[w] = cta_acc;
    __syncthreads();
    if (tid == 0) {
        float s = 0.f;
#pragma unroll
        for (int q = 0; q < 8; q++) s += red[q];
        atomicAdd(&g_part, (double)s);
    }

    // fused loss finish: last CTA to arrive does the pointwise pass
    __threadfence();
    __shared__ int lastflag;
    if (tid == 0) lastflag = (atomicAdd(&g_ctr, 1) == NPCTA - 1);
    __syncthreads();
    if (lastflag) {
        __shared__ float lpart;
        if (tid == 0) {
            double p = atomicAdd(&g_part, 0.0);   // coherent read
            lpart = logf((float)p);
        }
        __syncthreads();
        for (int el = tid; el < NBATCH; el += 256) {
            float den = (float)NDIM + g_den[el];
            float p = pij[el];
            out[el] = p * (logf(p) + logf(den) + lpart);
        }
    }
}

extern "C" void kernel_launch(void* const* d_in, const int* in_sizes, int n_in,
                              void* d_out, int out_size) {
    const float* pij        = (const float*)d_in[0];
    const float* noise_full = (const float*)d_in[1];
    const float* noise_i    = (const float*)d_in[2];
    const float* noise_j    = (const float*)d_in[3];
    const float* logits     = (const float*)d_in[4];
    const float* W          = (const float*)d_in[5];
    const int*   iv         = (const int*)d_in[7];
    const int*   jv         = (const int*)d_in[8];
    float* out = (float*)d_out;

    cudaFuncSetAttribute(k_gemm, cudaFuncAttributeMaxDynamicSharedMemorySize, SMEM_G);
    cudaFuncSetAttribute(k_pairwise, cudaFuncAttributeMaxDynamicSharedMemorySize, SMEM_PW);

    k_z<<<NROWS / 8, 256>>>(logits, noise_full, noise_i, noise_j, iv, jv);
    k_gemm<<<NROWS / 64, 256, SMEM_G>>>(W);
    k_pairwise<<<NPCTA, 256, SMEM_PW>>>(pij, out);
}

// round 16
// speedup vs baseline: 1.0123x; 1.0123x over previous
#include <cuda_runtime.h>
#include <cuda_bf16.h>
#include <math.h>
#include <cstdint>

#define NOBS   8192
#define NTOP   128
#define NDIM   64
#define NBATCH 8192
#define NROWS  (NOBS + NBATCH)
#define NTILE  64           // number of 128x128 tiles per dim (8192/128)
#define NTRI   2080         // triangular tile count = 64*65/2
#define NPCTA  296          // persistent CTAs (2 per SM)

// ------------------------- scratch (no cudaMalloc) -------------------------
__device__ float  g_X[NOBS * NDIM];    // tf32-rounded embedded points
__device__ float  g_sq[NOBS];          // sq norms of rounded points
__device__ float  g_den[NBATCH];       // partial loss: p*(log p + log(64+den))
__device__ double g_part;
__device__ int    g_ctr;

// ------------------------- helpers -----------------------------------------
__device__ __forceinline__ uint32_t smem_u32(const void* p) {
    uint32_t a;
    asm("{ .reg .u64 t; cvta.to.shared.u64 t, %1; cvt.u32.u64 %0, t; }" : "=r"(a) : "l"(p));
    return a;
}
__device__ __forceinline__ void cp16(uint32_t dst, const void* src) {
    asm volatile("{ .reg .u64 g; cvta.to.global.u64 g, %1; "
                 "cp.async.cg.shared.global [%0], [g], 16; }"
                 :: "r"(dst), "l"(src));
}
#define CP_COMMIT() asm volatile("cp.async.commit_group;" ::: "memory")
#define CP_WAIT0()  asm volatile("cp.async.wait_group 0;" ::: "memory")

__device__ __forceinline__ float fast_log_unit(float t) {
    float s = t - 1.0f;
    float p = fmaf(s, -0.16666667f, 0.2f);
    p = fmaf(s, p, -0.25f);
    p = fmaf(s, p, 0.33333333f);
    p = fmaf(s, p, -0.5f);
    p = fmaf(s, p, 1.0f);
    p = s * p;
    float lg = __logf(t);
    return (t > 0.90625f) ? p : lg;
}

__device__ __forceinline__ void gumbel_softmax4(const float* __restrict__ lrow,
                                                const float* __restrict__ nrow,
                                                int lane, float z[4]) {
    float s = 0.f;
#pragma unroll
    for (int c = 0; c < 4; c++) {
        int t = lane + 32 * c;
        float w = -fast_log_unit(nrow[t] + 1e-9f) + 1e-9f;
        z[c] = __fdividef(__expf(lrow[t]), w);
        s += z[c];
    }
#pragma unroll
    for (int o = 16; o > 0; o >>= 1) s += __shfl_xor_sync(0xffffffffu, s, o);
    float inv = __fdividef(1.f, s);
#pragma unroll
    for (int c = 0; c < 4; c++) z[c] *= inv;
}

__device__ __forceinline__ float tf32_round(float x) {
    uint32_t r;
    asm("cvt.rna.tf32.f32 %0, %1;" : "=r"(r) : "f"(x));
    return __uint_as_float(r);
}
__device__ __forceinline__ uint32_t tf32_hi(float x) {
    uint32_t r;
    asm("cvt.rna.tf32.f32 %0, %1;" : "=r"(r) : "f"(x));
    return r;
}
__device__ __forceinline__ void mma_tf32(float c[4], const uint32_t a[4], const uint32_t b[2]) {
    asm volatile(
        "mma.sync.aligned.m16n8k8.row.col.f32.tf32.tf32.f32 "
        "{%0,%1,%2,%3}, {%4,%5,%6,%7}, {%8,%9}, {%0,%1,%2,%3};"
        : "+f"(c[0]), "+f"(c[1]), "+f"(c[2]), "+f"(c[3])
        : "r"(a[0]), "r"(a[1]), "r"(a[2]), "r"(a[3]), "r"(b[0]), "r"(b[1]));
}
__device__ __forceinline__ float rcp_approx(float x) {
    float r;
    asm("rcp.approx.f32 %0, %1;" : "=f"(r) : "f"(x));
    return r;
}

// ---------------------------------------------------------------------------
// K1: fused z + GEMM. CTA owns 64 rows: computes gumbel-softmax z rows
// directly into swizzled smem, then X = Z @ W^T (tf32 x3, fp32-equivalent).
// Row sums accumulate in smem (no global zero pass needed).
//   rows < NOBS: store rounded x -> g_X, row sumsq -> g_sq
//   rows >= NOBS: g_den[el] = p*(log p + log(64+sumsq))   [loss partial]
// ---------------------------------------------------------------------------
#define G_ZS 0
#define G_WS 32768
#define SMEM_G 65536

__global__ void __launch_bounds__(256, 2) k_gemmz(const float* __restrict__ W,
                                                  const float* __restrict__ logits,
                                                  const float* __restrict__ noise_full,
                                                  const float* __restrict__ noise_i,
                                                  const float* __restrict__ noise_j,
                                                  const int* __restrict__ iv,
                                                  const int* __restrict__ jv,
                                                  const float* __restrict__ pij) {
    extern __shared__ char sm[];
    __shared__ float srow[64];
    int tid = threadIdx.x, w = tid >> 5, lane = tid & 31;
    int base = blockIdx.x * 64;
    bool zrows = (base < NOBS);

    if (blockIdx.x == 0 && tid == 0) { g_part = 0.0; g_ctr = 0; }
    if (tid < 64) srow[tid] = 0.f;

    {   // W tile: 32KB, swizzled rows of 512B
        const uint4* srcW = (const uint4*)W;
#pragma unroll
        for (int it = 0; it < 8; it++) {
            int idx = it * 256 + tid;
            int off = idx * 16;
            int row = off >> 9;
            uint32_t sw = (uint32_t)(off & ~511) | (uint32_t)((off & 511) ^ ((row & 7) << 4));
            *(uint4*)(sm + G_WS + sw) = srcW[idx];
        }
    }

    // z-phase: each warp computes 8 rows straight into swizzled smem
#pragma unroll 1
    for (int r = 0; r < 8; r++) {
        int rl = w * 8 + r;
        int row = base + rl;
        float z[4];
        if (zrows) {
            gumbel_softmax4(logits + (size_t)row * NTOP,
                            noise_full + (size_t)row * NTOP, lane, z);
        } else {
            int el = row - NOBS;
            int ri = iv[el], rj = jv[el];
            float zi[4], zj[4];
            gumbel_softmax4(logits + (size_t)ri * NTOP, noise_i + (size_t)el * NTOP, lane, zi);
            gumbel_softmax4(logits + (size_t)rj * NTOP, noise_j + (size_t)el * NTOP, lane, zj);
#pragma unroll
            for (int c = 0; c < 4; c++) z[c] = zi[c] - zj[c];
        }
#pragma unroll
        for (int c = 0; c < 4; c++) {
            int off = rl * 512 + (lane + 32 * c) * 4;
            uint32_t sw = (uint32_t)(off & ~511) | (uint32_t)((off & 511) ^ ((rl & 7) << 4));
            *(float*)(sm + G_ZS + sw) = z[c];
        }
    }
    __syncthreads();

    int mw = (w >> 2) * 32;
    int nw = (w & 3) * 16;
    int g = lane >> 2, t = lane & 3;

    float c[2][2][4];
#pragma unroll
    for (int mt = 0; mt < 2; mt++)
#pragma unroll
        for (int nt = 0; nt < 2; nt++)
#pragma unroll
            for (int q = 0; q < 4; q++) c[mt][nt][q] = 0.f;

#pragma unroll
    for (int ks = 0; ks < 16; ks++) {
        int c0 = (ks * 32 + 4 * t) ^ (g << 4);
        int c1 = (ks * 32 + 4 * t + 16) ^ (g << 4);

        uint32_t bh[2][2], bl[2][2];
#pragma unroll
        for (int nt = 0; nt < 2; nt++) {
            const char* rn = sm + G_WS + (nw + nt * 8 + g) * 512;
            float b0 = *(const float*)(rn + c0);
            float b1 = *(const float*)(rn + c1);
            bh[nt][0] = tf32_hi(b0);
            bh[nt][1] = tf32_hi(b1);
            bl[nt][0] = tf32_hi(b0 - __uint_as_float(bh[nt][0]));
            bl[nt][1] = tf32_hi(b1 - __uint_as_float(bh[nt][1]));
        }
        uint32_t ah[2][4], al[2][4];
#pragma unroll
        for (int mt = 0; mt < 2; mt++) {
            const char* r0 = sm + G_ZS + (mw + mt * 16 + g) * 512;
            const char* r1 = r0 + 8 * 512;
            float a0 = *(const float*)(r0 + c0);
            float a1 = *(const float*)(r1 + c0);
            float a2 = *(const float*)(r0 + c1);
            float a3 = *(const float*)(r1 + c1);
            ah[mt][0] = tf32_hi(a0); al[mt][0] = tf32_hi(a0 - __uint_as_float(ah[mt][0]));
            ah[mt][1] = tf32_hi(a1); al[mt][1] = tf32_hi(a1 - __uint_as_float(ah[mt][1]));
            ah[mt][2] = tf32_hi(a2); al[mt][2] = tf32_hi(a2 - __uint_as_float(ah[mt][2]));
            ah[mt][3] = tf32_hi(a3); al[mt][3] = tf32_hi(a3 - __uint_as_float(ah[mt][3]));
        }
#pragma unroll
        for (int mt = 0; mt < 2; mt++)
#pragma unroll
            for (int nt = 0; nt < 2; nt++) {
                mma_tf32(c[mt][nt], ah[mt], bh[nt]);
                mma_tf32(c[mt][nt], al[mt], bh[nt]);
                mma_tf32(c[mt][nt], ah[mt], bl[nt]);
            }
    }

#pragma unroll
    for (int mt = 0; mt < 2; mt++) {
        int ml = mw + mt * 16 + g;           // local row 0..63
        int m0 = base + ml;
        float r0 = 0.f, r1 = 0.f;
#pragma unroll
        for (int nt = 0; nt < 2; nt++) {
            int n0 = nw + nt * 8 + 2 * t;
            float v00 = c[mt][nt][0], v01 = c[mt][nt][1];
            float v10 = c[mt][nt][2], v11 = c[mt][nt][3];
            if (zrows) {
                v00 = tf32_round(v00); v01 = tf32_round(v01);
                v10 = tf32_round(v10); v11 = tf32_round(v11);
                g_X[(size_t)m0 * NDIM + n0]           = v00;
                g_X[(size_t)m0 * NDIM + n0 + 1]       = v01;
                g_X[(size_t)(m0 + 8) * NDIM + n0]     = v10;
                g_X[(size_t)(m0 + 8) * NDIM + n0 + 1] = v11;
            }
            r0 += fmaf(v00, v00, v01 * v01);
            r1 += fmaf(v10, v10, v11 * v11);
        }
        r0 += __shfl_xor_sync(0xffffffffu, r0, 1);
        r0 += __shfl_xor_sync(0xffffffffu, r0, 2);
        r1 += __shfl_xor_sync(0xffffffffu, r1, 1);
        r1 += __shfl_xor_sync(0xffffffffu, r1, 2);
        if (t == 0) {
            atomicAdd(&srow[ml], r0);
            atomicAdd(&srow[ml + 8], r1);
        }
    }
    __syncthreads();

    if (tid < 64) {
        if (zrows) {
            g_sq[base + tid] = srow[tid];
        } else {
            int el = base + tid - NOBS;
            float p = pij[el];
            g_den[el] = p * (logf(p) + logf((float)NDIM + srow[tid]));
        }
    }
}

// ---------------------------------------------------------------------------
// K2: persistent pairwise partition sum (R10-proven body) + last-CTA finish.
// A panel resident; B double-buffered via cp.async; diagonal reuses A.
// ---------------------------------------------------------------------------
#define P_A    0
#define P_B0   32768
#define P_B1   65536
#define P_RED  98304
#define SMEM_PW 98368

__device__ __forceinline__ void fill_async(uint32_t smbase, const float* gsrc, int tid) {
    const char* src = (const char*)gsrc;
#pragma unroll
    for (int it = 0; it < 8; it++) {
        int off = (it * 256 + tid) * 16;
        int row = off >> 8;
        uint32_t sw = (uint32_t)(off & ~255) | (uint32_t)((off & 255) ^ ((row & 7) << 4));
        cp16(smbase + sw, src + off);
    }
}

__device__ __forceinline__ void tile_compute(char* sm, uint32_t boff,
                                             int bi, int bj, bool diag, int tid) {
    int lane = tid & 31, w = tid >> 5;
    int mw = (w >> 2) * 64;
    int nw = (w & 3) * 32;
    int g = lane >> 2, t = lane & 3;

    float c[4][4][4];
#pragma unroll
    for (int mt = 0; mt < 4; mt++)
#pragma unroll
        for (int nt = 0; nt < 4; nt++)
#pragma unroll
            for (int q = 0; q < 4; q++) c[mt][nt][q] = 0.f;

#pragma unroll
    for (int ks = 0; ks < 8; ks++) {
        int c0 = (32 * ks + 4 * t) ^ (g << 4);
        int c1 = (32 * ks + 4 * t + 16) ^ (g << 4);

        uint32_t b[4][2];
#pragma unroll
        for (int nt = 0; nt < 4; nt++) {
            const char* rn = sm + boff + (nw + nt * 8 + g) * 256;
            b[nt][0] = *(const uint32_t*)(rn + c0);
            b[nt][1] = *(const uint32_t*)(rn + c1);
        }
        uint32_t a[4][4];
#pragma unroll
        for (int mt = 0; mt < 4; mt++) {
            const char* r0 = sm + P_A + (mw + mt * 16 + g) * 256;
            const char* r1 = r0 + 8 * 256;
            a[mt][0] = *(const uint32_t*)(r0 + c0);
            a[mt][1] = *(const uint32_t*)(r1 + c0);
            a[mt][2] = *(const uint32_t*)(r0 + c1);
            a[mt][3] = *(const uint32_t*)(r1 + c1);
        }
#pragma unroll
        for (int mt = 0; mt < 4; mt++)
#pragma unroll
            for (int nt = 0; nt < 4; nt++)
                mma_tf32(c[mt][nt], a[mt], b[nt]);
    }

    float sb0[4], sb1[4];
#pragma unroll
    for (int nt = 0; nt < 4; nt++) {
        int n0 = nw + nt * 8 + 2 * t;
        sb0[nt] = g_sq[bj * 128 + n0];
        sb1[nt] = g_sq[bj * 128 + n0 + 1];
    }
    float acc = 0.f;
#pragma unroll
    for (int mt = 0; mt < 4; mt++) {
        int m0 = mw + mt * 16 + g;
        float sa0 = g_sq[bi * 128 + m0];
        float sa1 = g_sq[bi * 128 + m0 + 8];
#pragma unroll
        for (int nt = 0; nt < 4; nt++) {
            int n0 = nw + nt * 8 + 2 * t;
            float v00 = rcp_approx(fmaf(-2.f, c[mt][nt][0], 1.f + sa0 + sb0[nt]));
            float v01 = rcp_approx(fmaf(-2.f, c[mt][nt][1], 1.f + sa0 + sb1[nt]));
            float v10 = rcp_approx(fmaf(-2.f, c[mt][nt][2], 1.f + sa1 + sb0[nt]));
            float v11 = rcp_approx(fmaf(-2.f, c[mt][nt][3], 1.f + sa1 + sb1[nt]));
            if (diag) {
                if (m0 == n0) v00 = 0.f;
                if (m0 == n0 + 1) v01 = 0.f;
                if (m0 + 8 == n0) v10 = 0.f;
                if (m0 + 8 == n0 + 1) v11 = 0.f;
            }
            acc += (v00 + v01) + (v10 + v11);
        }
    }
#pragma unroll
    for (int o = 16; o > 0; o >>= 1) acc += __shfl_xor_sync(0xffffffffu, acc, o);
    float* red = (float*)(sm + P_RED);
    if (lane == 0) red[w] = acc;
    __syncthreads();
    if (tid == 0) {
        float s = 0.f;
#pragma unroll
        for (int q = 0; q < 8; q++) s += red[q];
        atomicAdd(&g_part, (double)s * (diag ? 1.0 : 2.0));
    }
}

__global__ void __launch_bounds__(256, 2) k_pairwise(const float* __restrict__ pij,
                                                     float* __restrict__ out) {
    extern __shared__ char sm[];
    uint32_t smb = smem_u32(sm);
    int tid = threadIdx.x;
    int cid = blockIdx.x;

    int t0 = (NTRI * cid) / NPCTA;
    int t1 = (NTRI * (cid + 1)) / NPCTA;

    int bi = 0, rem = t0;
    while (rem >= NTILE - bi) { rem -= NTILE - bi; bi++; }
    int bj = bi + rem;

    fill_async(smb + P_A, g_X + (size_t)bi * 128 * NDIM, tid);
    int curbuf = 0, nextbuf = 0;
    if (bj != bi) {
        fill_async(smb + P_B0, g_X + (size_t)bj * 128 * NDIM, tid);
        nextbuf = 1;
    }
    CP_COMMIT();

#pragma unroll 1
    for (int t = t0; t < t1; t++) {
        int nbi = bi, nbj = bj + 1;
        if (nbj == NTILE) { nbi = bi + 1; nbj = nbi; }
        bool diag = (bi == bj);

        CP_WAIT0();
        __syncthreads();           // tile t data visible; all warps past tile t-1

        bool canPre = (t + 1 < t1) && (nbi == bi);
        if (canPre) {
            fill_async(smb + (nextbuf ? P_B1 : P_B0),
                       g_X + (size_t)nbj * 128 * NDIM, tid);
            CP_COMMIT();
        }

        tile_compute(sm, diag ? P_A : (curbuf ? P_B1 : P_B0), bi, bj, diag, tid);

        if (canPre) { curbuf = nextbuf; nextbuf ^= 1; }
        bi = nbi; bj = nbj;
        if (t + 1 < t1 && !canPre) {
            __syncthreads();
            fill_async(smb + P_A, g_X + (size_t)bi * 128 * NDIM, tid);
            CP_COMMIT();
        }
    }

    // fused loss finish: last CTA adds the log(part) term (no transcendentals
    // in the loop — partials precomputed in k_gemmz)
    __threadfence();
    __shared__ int lastflag;
    if (tid == 0) lastflag = (atomicAdd(&g_ctr, 1) == NPCTA - 1) ? 1 : 0;
    __syncthreads();
    if (lastflag) {
        __shared__ float lpart;
        if (tid == 0) {
            double p = atomicAdd(&g_part, 0.0);   // coherent read
            lpart = logf((float)p);
        }
        __syncthreads();
#pragma unroll 4
        for (int el = tid; el < NBATCH; el += 256)
            out[el] = fmaf(pij[el], lpart, g_den[el]);
    }
}

extern "C" void kernel_launch(void* const* d_in, const int* in_sizes, int n_in,
                              void* d_out, int out_size) {
    const float* pij        = (const float*)d_in[0];
    const float* noise_full = (const float*)d_in[1];
    const float* noise_i    = (const float*)d_in[2];
    const float* noise_j    = (const float*)d_in[3];
    const float* logits     = (const float*)d_in[4];
    const float* W          = (const float*)d_in[5];
    const int*   iv         = (const int*)d_in[7];
    const int*   jv         = (const int*)d_in[8];
    float* out = (float*)d_out;

    cudaFuncSetAttribute(k_gemmz, cudaFuncAttributeMaxDynamicSharedMemorySize, SMEM_G);
    cudaFuncSetAttribute(k_pairwise, cudaFuncAttributeMaxDynamicSharedMemorySize, SMEM_PW);

    k_gemmz<<<NROWS / 64, 256, SMEM_G>>>(W, logits, noise_full, noise_i, noise_j,
                                         iv, jv, pij);
    k_pairwise<<<NPCTA, 256, SMEM_PW>>>(pij, out);
}

// round 17
// speedup vs baseline: 1.1416x; 1.1277x over previous
#include <cuda_runtime.h>
#include <cuda_bf16.h>
#include <math.h>
#include <cstdint>

#define NOBS   8192
#define NTOP   128
#define NDIM   64
#define NBATCH 8192
#define NROWS  (NOBS + NBATCH)
#define NTILE  64           // number of 128x128 tiles per dim (8192/128)
#define NTRI   2080         // triangular tile count = 64*65/2
#define NPCTA  296          // persistent CTAs (2 per SM)

// ------------------------- scratch (no cudaMalloc) -------------------------
__device__ float  g_X[NOBS * NDIM];    // tf32-rounded embedded points
__device__ float  g_sq[NOBS];          // sq norms of rounded points
__device__ float  g_den[NBATCH];       // partial loss: p*(log p + log(64+den))
__device__ double g_part;

// ------------------------- helpers -----------------------------------------
__device__ __forceinline__ uint32_t smem_u32(const void* p) {
    uint32_t a;
    asm("{ .reg .u64 t; cvta.to.shared.u64 t, %1; cvt.u32.u64 %0, t; }" : "=r"(a) : "l"(p));
    return a;
}
__device__ __forceinline__ void cp16(uint32_t dst, const void* src) {
    asm volatile("{ .reg .u64 g; cvta.to.global.u64 g, %1; "
                 "cp.async.cg.shared.global [%0], [g], 16; }"
                 :: "r"(dst), "l"(src));
}
#define CP_COMMIT() asm volatile("cp.async.commit_group;" ::: "memory")
#define CP_WAIT0()  asm volatile("cp.async.wait_group 0;" ::: "memory")

__device__ __forceinline__ float fast_log_unit(float t) {
    float s = t - 1.0f;
    float p = fmaf(s, -0.16666667f, 0.2f);
    p = fmaf(s, p, -0.25f);
    p = fmaf(s, p, 0.33333333f);
    p = fmaf(s, p, -0.5f);
    p = fmaf(s, p, 1.0f);
    p = s * p;
    float lg = __logf(t);
    return (t > 0.90625f) ? p : lg;
}

__device__ __forceinline__ void gumbel_softmax4(const float* __restrict__ lrow,
                                                const float* __restrict__ nrow,
                                                int lane, float z[4]) {
    float s = 0.f;
#pragma unroll
    for (int c = 0; c < 4; c++) {
        int t = lane + 32 * c;
        float w = -fast_log_unit(nrow[t] + 1e-9f) + 1e-9f;
        z[c] = __fdividef(__expf(lrow[t]), w);
        s += z[c];
    }
#pragma unroll
    for (int o = 16; o > 0; o >>= 1) s += __shfl_xor_sync(0xffffffffu, s, o);
    float inv = __fdividef(1.f, s);
#pragma unroll
    for (int c = 0; c < 4; c++) z[c] *= inv;
}

__device__ __forceinline__ float tf32_round(float x) {
    uint32_t r;
    asm("cvt.rna.tf32.f32 %0, %1;" : "=r"(r) : "f"(x));
    return __uint_as_float(r);
}
__device__ __forceinline__ uint32_t tf32_hi(float x) {
    uint32_t r;
    asm("cvt.rna.tf32.f32 %0, %1;" : "=r"(r) : "f"(x));
    return r;
}
__device__ __forceinline__ void mma_tf32(float c[4], const uint32_t a[4], const uint32_t b[2]) {
    asm volatile(
        "mma.sync.aligned.m16n8k8.row.col.f32.tf32.tf32.f32 "
        "{%0,%1,%2,%3}, {%4,%5,%6,%7}, {%8,%9}, {%0,%1,%2,%3};"
        : "+f"(c[0]), "+f"(c[1]), "+f"(c[2]), "+f"(c[3])
        : "r"(a[0]), "r"(a[1]), "r"(a[2]), "r"(a[3]), "r"(b[0]), "r"(b[1]));
}
__device__ __forceinline__ float rcp_approx(float x) {
    float r;
    asm("rcp.approx.f32 %0, %1;" : "=f"(r) : "f"(x));
    return r;
}

// ---------------------------------------------------------------------------
// K1: fused z + GEMM (proven 6.2us). CTA owns 64 rows: gumbel-softmax direct
// into swizzled smem, then X = Z @ W^T (tf32 x3, fp32-equivalent).
//   rows < NOBS: store rounded x -> g_X, row sumsq -> g_sq
//   rows >= NOBS: g_den[el] = p*(log p + log(64+sumsq))   [loss partial]
// ---------------------------------------------------------------------------
#define G_ZS 0
#define G_WS 32768
#define SMEM_G 65536

__global__ void __launch_bounds__(256, 2) k_gemmz(const float* __restrict__ W,
                                                  const float* __restrict__ logits,
                                                  const float* __restrict__ noise_full,
                                                  const float* __restrict__ noise_i,
                                                  const float* __restrict__ noise_j,
                                                  const int* __restrict__ iv,
                                                  const int* __restrict__ jv,
                                                  const float* __restrict__ pij) {
    extern __shared__ char sm[];
    __shared__ float srow[64];
    int tid = threadIdx.x, w = tid >> 5, lane = tid & 31;
    int base = blockIdx.x * 64;
    bool zrows = (base < NOBS);

    if (blockIdx.x == 0 && tid == 0) g_part = 0.0;
    if (tid < 64) srow[tid] = 0.f;

    {   // W tile: 32KB, swizzled rows of 512B
        const uint4* srcW = (const uint4*)W;
#pragma unroll
        for (int it = 0; it < 8; it++) {
            int idx = it * 256 + tid;
            int off = idx * 16;
            int row = off >> 9;
            uint32_t sw = (uint32_t)(off & ~511) | (uint32_t)((off & 511) ^ ((row & 7) << 4));
            *(uint4*)(sm + G_WS + sw) = srcW[idx];
        }
    }

    // z-phase: each warp computes 8 rows straight into swizzled smem
#pragma unroll 1
    for (int r = 0; r < 8; r++) {
        int rl = w * 8 + r;
        int row = base + rl;
        float z[4];
        if (zrows) {
            gumbel_softmax4(logits + (size_t)row * NTOP,
                            noise_full + (size_t)row * NTOP, lane, z);
        } else {
            int el = row - NOBS;
            int ri = iv[el], rj = jv[el];
            float zi[4], zj[4];
            gumbel_softmax4(logits + (size_t)ri * NTOP, noise_i + (size_t)el * NTOP, lane, zi);
            gumbel_softmax4(logits + (size_t)rj * NTOP, noise_j + (size_t)el * NTOP, lane, zj);
#pragma unroll
            for (int c = 0; c < 4; c++) z[c] = zi[c] - zj[c];
        }
#pragma unroll
        for (int c = 0; c < 4; c++) {
            int off = rl * 512 + (lane + 32 * c) * 4;
            uint32_t sw = (uint32_t)(off & ~511) | (uint32_t)((off & 511) ^ ((rl & 7) << 4));
            *(float*)(sm + G_ZS + sw) = z[c];
        }
    }
    __syncthreads();

    int mw = (w >> 2) * 32;
    int nw = (w & 3) * 16;
    int g = lane >> 2, t = lane & 3;

    float c[2][2][4];
#pragma unroll
    for (int mt = 0; mt < 2; mt++)
#pragma unroll
        for (int nt = 0; nt < 2; nt++)
#pragma unroll
            for (int q = 0; q < 4; q++) c[mt][nt][q] = 0.f;

#pragma unroll
    for (int ks = 0; ks < 16; ks++) {
        int c0 = (ks * 32 + 4 * t) ^ (g << 4);
        int c1 = (ks * 32 + 4 * t + 16) ^ (g << 4);

        uint32_t bh[2][2], bl[2][2];
#pragma unroll
        for (int nt = 0; nt < 2; nt++) {
            const char* rn = sm + G_WS + (nw + nt * 8 + g) * 512;
            float b0 = *(const float*)(rn + c0);
            float b1 = *(const float*)(rn + c1);
            bh[nt][0] = tf32_hi(b0);
            bh[nt][1] = tf32_hi(b1);
            bl[nt][0] = tf32_hi(b0 - __uint_as_float(bh[nt][0]));
            bl[nt][1] = tf32_hi(b1 - __uint_as_float(bh[nt][1]));
        }
        uint32_t ah[2][4], al[2][4];
#pragma unroll
        for (int mt = 0; mt < 2; mt++) {
            const char* r0 = sm + G_ZS + (mw + mt * 16 + g) * 512;
            const char* r1 = r0 + 8 * 512;
            float a0 = *(const float*)(r0 + c0);
            float a1 = *(const float*)(r1 + c0);
            float a2 = *(const float*)(r0 + c1);
            float a3 = *(const float*)(r1 + c1);
            ah[mt][0] = tf32_hi(a0); al[mt][0] = tf32_hi(a0 - __uint_as_float(ah[mt][0]));
            ah[mt][1] = tf32_hi(a1); al[mt][1] = tf32_hi(a1 - __uint_as_float(ah[mt][1]));
            ah[mt][2] = tf32_hi(a2); al[mt][2] = tf32_hi(a2 - __uint_as_float(ah[mt][2]));
            ah[mt][3] = tf32_hi(a3); al[mt][3] = tf32_hi(a3 - __uint_as_float(ah[mt][3]));
        }
#pragma unroll
        for (int mt = 0; mt < 2; mt++)
#pragma unroll
            for (int nt = 0; nt < 2; nt++) {
                mma_tf32(c[mt][nt], ah[mt], bh[nt]);
                mma_tf32(c[mt][nt], al[mt], bh[nt]);
                mma_tf32(c[mt][nt], ah[mt], bl[nt]);
            }
    }

#pragma unroll
    for (int mt = 0; mt < 2; mt++) {
        int ml = mw + mt * 16 + g;           // local row 0..63
        int m0 = base + ml;
        float r0 = 0.f, r1 = 0.f;
#pragma unroll
        for (int nt = 0; nt < 2; nt++) {
            int n0 = nw + nt * 8 + 2 * t;
            float v00 = c[mt][nt][0], v01 = c[mt][nt][1];
            float v10 = c[mt][nt][2], v11 = c[mt][nt][3];
            if (zrows) {
                v00 = tf32_round(v00); v01 = tf32_round(v01);
                v10 = tf32_round(v10); v11 = tf32_round(v11);
                g_X[(size_t)m0 * NDIM + n0]           = v00;
                g_X[(size_t)m0 * NDIM + n0 + 1]       = v01;
                g_X[(size_t)(m0 + 8) * NDIM + n0]     = v10;
                g_X[(size_t)(m0 + 8) * NDIM + n0 + 1] = v11;
            }
            r0 += fmaf(v00, v00, v01 * v01);
            r1 += fmaf(v10, v10, v11 * v11);
        }
        r0 += __shfl_xor_sync(0xffffffffu, r0, 1);
        r0 += __shfl_xor_sync(0xffffffffu, r0, 2);
        r1 += __shfl_xor_sync(0xffffffffu, r1, 1);
        r1 += __shfl_xor_sync(0xffffffffu, r1, 2);
        if (t == 0) {
            atomicAdd(&srow[ml], r0);
            atomicAdd(&srow[ml + 8], r1);
        }
    }
    __syncthreads();

    if (tid < 64) {
        if (zrows) {
            g_sq[base + tid] = srow[tid];
        } else {
            int el = base + tid - NOBS;
            float p = pij[el];
            g_den[el] = p * (logf(p) + logf((float)NDIM + srow[tid]));
        }
    }
}

// ---------------------------------------------------------------------------
// K2: persistent pairwise partition sum — EXACT R10 body (125 regs, no tail,
// no extra args: the fused tail pushed regs to the 128 cap and spilled the
// mainloop accumulators, +20us). A panel resident; B double-buffered.
// ---------------------------------------------------------------------------
#define P_A    0
#define P_B0   32768
#define P_B1   65536
#define P_RED  98304
#define SMEM_PW 98368

__device__ __forceinline__ void fill_async(uint32_t smbase, const float* gsrc, int tid) {
    const char* src = (const char*)gsrc;
#pragma unroll
    for (int it = 0; it < 8; it++) {
        int off = (it * 256 + tid) * 16;
        int row = off >> 8;
        uint32_t sw = (uint32_t)(off & ~255) | (uint32_t)((off & 255) ^ ((row & 7) << 4));
        cp16(smbase + sw, src + off);
    }
}

__device__ __forceinline__ void tile_compute(char* sm, uint32_t boff,
                                             int bi, int bj, bool diag, int tid) {
    int lane = tid & 31, w = tid >> 5;
    int mw = (w >> 2) * 64;
    int nw = (w & 3) * 32;
    int g = lane >> 2, t = lane & 3;

    float c[4][4][4];
#pragma unroll
    for (int mt = 0; mt < 4; mt++)
#pragma unroll
        for (int nt = 0; nt < 4; nt++)
#pragma unroll
            for (int q = 0; q < 4; q++) c[mt][nt][q] = 0.f;

#pragma unroll
    for (int ks = 0; ks < 8; ks++) {
        int c0 = (32 * ks + 4 * t) ^ (g << 4);
        int c1 = (32 * ks + 4 * t + 16) ^ (g << 4);

        uint32_t b[4][2];
#pragma unroll
        for (int nt = 0; nt < 4; nt++) {
            const char* rn = sm + boff + (nw + nt * 8 + g) * 256;
            b[nt][0] = *(const uint32_t*)(rn + c0);
            b[nt][1] = *(const uint32_t*)(rn + c1);
        }
        uint32_t a[4][4];
#pragma unroll
        for (int mt = 0; mt < 4; mt++) {
            const char* r0 = sm + P_A + (mw + mt * 16 + g) * 256;
            const char* r1 = r0 + 8 * 256;
            a[mt][0] = *(const uint32_t*)(r0 + c0);
            a[mt][1] = *(const uint32_t*)(r1 + c0);
            a[mt][2] = *(const uint32_t*)(r0 + c1);
            a[mt][3] = *(const uint32_t*)(r1 + c1);
        }
#pragma unroll
        for (int mt = 0; mt < 4; mt++)
#pragma unroll
            for (int nt = 0; nt < 4; nt++)
                mma_tf32(c[mt][nt], a[mt], b[nt]);
    }

    float sb0[4], sb1[4];
#pragma unroll
    for (int nt = 0; nt < 4; nt++) {
        int n0 = nw + nt * 8 + 2 * t;
        sb0[nt] = g_sq[bj * 128 + n0];
        sb1[nt] = g_sq[bj * 128 + n0 + 1];
    }
    float acc = 0.f;
#pragma unroll
    for (int mt = 0; mt < 4; mt++) {
        int m0 = mw + mt * 16 + g;
        float sa0 = g_sq[bi * 128 + m0];
        float sa1 = g_sq[bi * 128 + m0 + 8];
#pragma unroll
        for (int nt = 0; nt < 4; nt++) {
            int n0 = nw + nt * 8 + 2 * t;
            float v00 = rcp_approx(fmaf(-2.f, c[mt][nt][0], 1.f + sa0 + sb0[nt]));
            float v01 = rcp_approx(fmaf(-2.f, c[mt][nt][1], 1.f + sa0 + sb1[nt]));
            float v10 = rcp_approx(fmaf(-2.f, c[mt][nt][2], 1.f + sa1 + sb0[nt]));
            float v11 = rcp_approx(fmaf(-2.f, c[mt][nt][3], 1.f + sa1 + sb1[nt]));
            if (diag) {
                if (m0 == n0) v00 = 0.f;
                if (m0 == n0 + 1) v01 = 0.f;
                if (m0 + 8 == n0) v10 = 0.f;
                if (m0 + 8 == n0 + 1) v11 = 0.f;
            }
            acc += (v00 + v01) + (v10 + v11);
        }
    }
#pragma unroll
    for (int o = 16; o > 0; o >>= 1) acc += __shfl_xor_sync(0xffffffffu, acc, o);
    float* red = (float*)(sm + P_RED);
    if (lane == 0) red[w] = acc;
    __syncthreads();
    if (tid == 0) {
        float s = 0.f;
#pragma unroll
        for (int q = 0; q < 8; q++) s += red[q];
        atomicAdd(&g_part, (double)s * (diag ? 1.0 : 2.0));
    }
}

__global__ void __launch_bounds__(256, 2) k_pairwise() {
    extern __shared__ char sm[];
    uint32_t smb = smem_u32(sm);
    int tid = threadIdx.x;
    int cid = blockIdx.x;

    int t0 = (NTRI * cid) / NPCTA;
    int t1 = (NTRI * (cid + 1)) / NPCTA;

    int bi = 0, rem = t0;
    while (rem >= NTILE - bi) { rem -= NTILE - bi; bi++; }
    int bj = bi + rem;

    fill_async(smb + P_A, g_X + (size_t)bi * 128 * NDIM, tid);
    int curbuf = 0, nextbuf = 0;
    if (bj != bi) {
        fill_async(smb + P_B0, g_X + (size_t)bj * 128 * NDIM, tid);
        nextbuf = 1;
    }
    CP_COMMIT();

#pragma unroll 1
    for (int t = t0; t < t1; t++) {
        int nbi = bi, nbj = bj + 1;
        if (nbj == NTILE) { nbi = bi + 1; nbj = nbi; }
        bool diag = (bi == bj);

        CP_WAIT0();
        __syncthreads();           // tile t data visible; all warps past tile t-1

        bool canPre = (t + 1 < t1) && (nbi == bi);
        if (canPre) {
            fill_async(smb + (nextbuf ? P_B1 : P_B0),
                       g_X + (size_t)nbj * 128 * NDIM, tid);
            CP_COMMIT();
        }

        tile_compute(sm, diag ? P_A : (curbuf ? P_B1 : P_B0), bi, bj, diag, tid);

        if (canPre) { curbuf = nextbuf; nextbuf ^= 1; }
        bi = nbi; bj = nbj;
        if (t + 1 < t1 && !canPre) {
            __syncthreads();
            fill_async(smb + P_A, g_X + (size_t)bi * 128 * NDIM, tid);
            CP_COMMIT();
        }
    }
}

// ---------------------------------------------------------------------------
// K3: trivial loss finish — partials precomputed, one log(part) per block.
// ---------------------------------------------------------------------------
__global__ void __launch_bounds__(256) k_loss_fin(const float* __restrict__ pij,
                                                  float* __restrict__ out) {
    __shared__ float lpart;
    if (threadIdx.x == 0) lpart = logf((float)g_part);
    __syncthreads();
    int el = blockIdx.x * 256 + threadIdx.x;
    out[el] = fmaf(pij[el], lpart, g_den[el]);
}

extern "C" void kernel_launch(void* const* d_in, const int* in_sizes, int n_in,
                              void* d_out, int out_size) {
    const float* pij        = (const float*)d_in[0];
    const float* noise_full = (const float*)d_in[1];
    const float* noise_i    = (const float*)d_in[2];
    const float* noise_j    = (const float*)d_in[3];
    const float* logits     = (const float*)d_in[4];
    const float* W          = (const float*)d_in[5];
    const int*   iv         = (const int*)d_in[7];
    const int*   jv         = (const int*)d_in[8];
    float* out = (float*)d_out;

    cudaFuncSetAttribute(k_gemmz, cudaFuncAttributeMaxDynamicSharedMemorySize, SMEM_G);
    cudaFuncSetAttribute(k_pairwise, cudaFuncAttributeMaxDynamicSharedMemorySize, SMEM_PW);

    k_gemmz<<<NROWS / 64, 256, SMEM_G>>>(W, logits, noise_full, noise_i, noise_j,
                                         iv, jv, pij);
    k_pairwise<<<NPCTA, 256, SMEM_PW>>>();
    k_loss_fin<<<NBATCH / 256, 256>>>(pij, out);
}